// round 1
// baseline (speedup 1.0000x reference)
#include <cuda_runtime.h>
#include <cstdint>

#define DIN   256
#define DOUT  128
#define NMAX  100000

// Scratch (static device globals — allocation-free per harness rules)
__device__ float g_h  [(size_t)NMAX * DOUT];   // 51.2 MB: transformed features
__device__ float g_agg[(size_t)NMAX * DOUT];   // 51.2 MB: aggregation accumulator
__device__ int   g_outdeg[NMAX];
__device__ int   g_indeg [NMAX];
__device__ float g_scout [NMAX];               // out_deg^-1/2
__device__ float g_scin  [NMAX];               // in_deg^-1/2

// ---------------------------------------------------------------- degree zero
__global__ void k_zero_deg(int n) {
    int i = blockIdx.x * blockDim.x + threadIdx.x;
    if (i < n) { g_outdeg[i] = 0; g_indeg[i] = 0; }
}

// ---------------------------------------------------------------- degree count
__global__ void k_count(const int* __restrict__ src, const int* __restrict__ dst, int nE) {
    int i = blockIdx.x * blockDim.x + threadIdx.x;
    if (i < nE) {
        atomicAdd(&g_outdeg[src[i]], 1);
        atomicAdd(&g_indeg [dst[i]], 1);
    }
}

// ---------------------------------------------------------------- scales
__global__ void k_scales(int n) {
    int i = blockIdx.x * blockDim.x + threadIdx.x;
    if (i < n) {
        g_scout[i] = rsqrtf(fmaxf((float)g_outdeg[i], 1.0f));
        g_scin [i] = rsqrtf(fmaxf((float)g_indeg [i], 1.0f));
    }
}

// ---------------------------------------------------------------- GEMM
// h[i,:] = (feat[i,:] * scout[i]) @ W      [M,256]x[256,128] -> [M,128]
// BM=128, BN=128(full), BK=16; 256 threads; 8x8 micro-tile per thread.
// Also zeros g_agg for the same rows (saves a separate memset pass).
#define BM 128
#define BN 128
#define BK 16
#define TM 8
#define TN 8

__global__ __launch_bounds__(256) void k_gemm(const float* __restrict__ feat,
                                              const float* __restrict__ weight,
                                              int M) {
    __shared__ float As[BM][BK];   // row-major tile of scaled A
    __shared__ float Bs[BK][BN];

    const int block_row = blockIdx.x * BM;
    const int tid = threadIdx.x;
    const int tr = (tid / 16) * TM;      // 0..120
    const int tc = (tid % 16) * TN;      // 0..120

    float acc[TM][TN];
    #pragma unroll
    for (int i = 0; i < TM; i++)
        #pragma unroll
        for (int j = 0; j < TN; j++) acc[i][j] = 0.0f;

    for (int k0 = 0; k0 < DIN; k0 += BK) {
        // Load A tile: 128 rows x 16 cols = 512 float4; 2 per thread.
        #pragma unroll
        for (int i = 0; i < 2; i++) {
            int idx = tid + i * 256;           // 0..511
            int r   = idx >> 2;                // tile row 0..127
            int c4  = (idx & 3) * 4;           // col 0,4,8,12
            int grow = block_row + r;
            float4 v = make_float4(0.f, 0.f, 0.f, 0.f);
            float  s = 0.f;
            if (grow < M) {
                v = *(const float4*)&feat[(size_t)grow * DIN + k0 + c4];
                s = g_scout[grow];
            }
            *(float4*)&As[r][c4] = make_float4(v.x * s, v.y * s, v.z * s, v.w * s);
        }
        // Load B tile: 16 rows x 128 cols = 512 float4; 2 per thread.
        #pragma unroll
        for (int i = 0; i < 2; i++) {
            int idx = tid + i * 256;
            int r   = idx >> 5;                // 0..15
            int c4  = (idx & 31) * 4;          // 0..124
            *(float4*)&Bs[r][c4] = *(const float4*)&weight[(size_t)(k0 + r) * DOUT + c4];
        }
        __syncthreads();

        #pragma unroll
        for (int k = 0; k < BK; k++) {
            float a[TM], b[TN];
            #pragma unroll
            for (int i = 0; i < TM; i++) a[i] = As[tr + i][k];
            float4 b0 = *(float4*)&Bs[k][tc];
            float4 b1 = *(float4*)&Bs[k][tc + 4];
            b[0]=b0.x; b[1]=b0.y; b[2]=b0.z; b[3]=b0.w;
            b[4]=b1.x; b[5]=b1.y; b[6]=b1.z; b[7]=b1.w;
            #pragma unroll
            for (int i = 0; i < TM; i++)
                #pragma unroll
                for (int j = 0; j < TN; j++)
                    acc[i][j] = fmaf(a[i], b[j], acc[i][j]);
        }
        __syncthreads();
    }

    // Epilogue: write h, zero agg for these rows.
    #pragma unroll
    for (int i = 0; i < TM; i++) {
        int grow = block_row + tr + i;
        if (grow < M) {
            #pragma unroll
            for (int j = 0; j < TN; j += 4) {
                *(float4*)&g_h  [(size_t)grow * DOUT + tc + j] =
                    make_float4(acc[i][j], acc[i][j+1], acc[i][j+2], acc[i][j+3]);
                *(float4*)&g_agg[(size_t)grow * DOUT + tc + j] =
                    make_float4(0.f, 0.f, 0.f, 0.f);
            }
        }
    }
}

// ---------------------------------------------------------------- edge scatter
// One warp per edge: 32 lanes x float4 = 128 floats. Gather h[src] (L2-resident),
// vectorized red.global.add.v4.f32 into agg[dst] (quarter the LTS atomic ops of
// scalar atomicAdd).
__global__ __launch_bounds__(256) void k_scatter(const int* __restrict__ src,
                                                 const int* __restrict__ dst,
                                                 int nE) {
    long gid  = (long)blockIdx.x * blockDim.x + threadIdx.x;
    long e    = gid >> 5;
    int  lane = (int)(gid & 31);
    if (e >= nE) return;
    int s = __ldg(&src[e]);
    int d = __ldg(&dst[e]);
    float4 v = __ldg((const float4*)g_h + (size_t)s * 32 + lane);
    float* ap = g_agg + (size_t)d * DOUT + lane * 4;
    asm volatile("red.global.add.v4.f32 [%0], {%1,%2,%3,%4};"
                 :: "l"(ap), "f"(v.x), "f"(v.y), "f"(v.z), "f"(v.w)
                 : "memory");
}

// ---------------------------------------------------------------- finalize
// out[i,c] = agg[i,c] * scin[i] + bias[c]
__global__ void k_finalize(float* __restrict__ out,
                           const float* __restrict__ bias,
                           int M) {
    long i = (long)blockIdx.x * blockDim.x + threadIdx.x;   // float4 index
    long total = (long)M * (DOUT / 4);
    if (i >= total) return;
    int node = (int)(i >> 5);          // DOUT/4 = 32 float4 per node
    int c4   = (int)(i & 31) * 4;
    float s = g_scin[node];
    float4 a = *((const float4*)g_agg + i);
    float4 b = *(const float4*)&bias[c4];
    float4 r = make_float4(fmaf(a.x, s, b.x), fmaf(a.y, s, b.y),
                           fmaf(a.z, s, b.z), fmaf(a.w, s, b.w));
    *((float4*)out + i) = r;
}

// ---------------------------------------------------------------- launch
extern "C" void kernel_launch(void* const* d_in, const int* in_sizes, int n_in,
                              void* d_out, int out_size) {
    const float* feat   = (const float*)d_in[0];
    const float* weight = (const float*)d_in[1];
    const float* bias   = (const float*)d_in[2];
    const int*   src    = (const int*)  d_in[3];
    const int*   dst    = (const int*)  d_in[4];

    int M  = in_sizes[0] / DIN;   // 100000
    int nE = in_sizes[3];         // 3200000

    k_zero_deg<<<(M + 255) / 256, 256>>>(M);
    k_count   <<<(nE + 255) / 256, 256>>>(src, dst, nE);
    k_scales  <<<(M + 255) / 256, 256>>>(M);
    k_gemm    <<<(M + BM - 1) / BM, 256>>>(feat, weight, M);

    long scatter_threads = (long)nE * 32;
    k_scatter <<<(unsigned)((scatter_threads + 255) / 256), 256>>>(src, dst, nE);

    long fin = (long)M * (DOUT / 4);
    k_finalize<<<(unsigned)((fin + 255) / 256), 256>>>((float*)d_out, bias, M);
}

// round 2
// speedup vs baseline: 1.7279x; 1.7279x over previous
#include <cuda_runtime.h>
#include <cstdint>

#define DIN   256
#define DOUT  128
#define NMAX  100000
#define EMAX  3200000

// Scratch (static device globals — allocation-free per harness rules)
__device__ float g_h   [(size_t)NMAX * DOUT];  // 51.2 MB: transformed features
__device__ int   g_outdeg[NMAX];
__device__ int   g_indeg [NMAX];
__device__ float g_scout [NMAX];               // out_deg^-1/2
__device__ float g_scin  [NMAX];               // in_deg^-1/2
__device__ int   g_off   [NMAX + 1];           // CSR offsets (by dst)
__device__ int   g_cursor[NMAX];               // placement cursors
__device__ int   g_bsum  [1024];               // block sums for scan
__device__ int   g_csrc  [EMAX];               // CSR payload: src node per slot

// ---------------------------------------------------------------- degree zero
__global__ void k_zero_deg(int n) {
    int i = blockIdx.x * blockDim.x + threadIdx.x;
    if (i < n) { g_outdeg[i] = 0; g_indeg[i] = 0; }
}

// ---------------------------------------------------------------- degree count
__global__ void k_count(const int* __restrict__ src, const int* __restrict__ dst, int nE) {
    int i = blockIdx.x * blockDim.x + threadIdx.x;
    if (i < nE) {
        atomicAdd(&g_outdeg[src[i]], 1);
        atomicAdd(&g_indeg [dst[i]], 1);
    }
}

// ---------------------------------------------------------------- scales
__global__ void k_scales(int n) {
    int i = blockIdx.x * blockDim.x + threadIdx.x;
    if (i < n) {
        g_scout[i] = rsqrtf(fmaxf((float)g_outdeg[i], 1.0f));
        g_scin [i] = rsqrtf(fmaxf((float)g_indeg [i], 1.0f));
    }
}

// ---------------------------------------------------------------- scan stage 1
// Per-block exclusive scan of g_indeg into g_off; block totals into g_bsum.
__global__ __launch_bounds__(256) void k_scan1(int n) {
    __shared__ int sh[256];
    int i = blockIdx.x * 256 + threadIdx.x;
    int v = (i < n) ? g_indeg[i] : 0;
    sh[threadIdx.x] = v;
    __syncthreads();
    #pragma unroll
    for (int off = 1; off < 256; off <<= 1) {
        int t = (threadIdx.x >= off) ? sh[threadIdx.x - off] : 0;
        __syncthreads();
        sh[threadIdx.x] += t;
        __syncthreads();
    }
    if (i < n) g_off[i] = sh[threadIdx.x] - v;       // exclusive within block
    if (threadIdx.x == 255) g_bsum[blockIdx.x] = sh[255];
}

// ---------------------------------------------------------------- scan stage 2
// Single block: exclusive scan of nb block sums (nb <= 1024).
__global__ __launch_bounds__(1024) void k_scan2(int nb) {
    __shared__ int sh[1024];
    int t = threadIdx.x;
    int v = (t < nb) ? g_bsum[t] : 0;
    sh[t] = v;
    __syncthreads();
    #pragma unroll
    for (int off = 1; off < 1024; off <<= 1) {
        int x = (t >= off) ? sh[t - off] : 0;
        __syncthreads();
        sh[t] += x;
        __syncthreads();
    }
    if (t < nb) g_bsum[t] = sh[t] - v;               // exclusive
}

// ---------------------------------------------------------------- scan stage 3
// Add block offsets; init cursors; write sentinel.
__global__ void k_scan3(int n, int nE) {
    int i = blockIdx.x * blockDim.x + threadIdx.x;
    if (i < n) {
        int o = g_off[i] + g_bsum[blockIdx.x * 256 / 256 == 0 ? blockIdx.x : blockIdx.x]; // (blockIdx) — see below
        o = g_off[i] + g_bsum[blockIdx.x];
        g_off[i] = o;
        g_cursor[i] = o;
    }
    if (i == 0) g_off[n] = nE;
}

// ---------------------------------------------------------------- CSR build
// Place src id of each edge into its dst bucket.
__global__ void k_build(const int* __restrict__ src, const int* __restrict__ dst, int nE) {
    int i = blockIdx.x * blockDim.x + threadIdx.x;
    if (i < nE) {
        int d = dst[i];
        int p = atomicAdd(&g_cursor[d], 1);
        g_csrc[p] = src[i];
    }
}

// ---------------------------------------------------------------- GEMM
// h[i,:] = (feat[i,:] * scout[i]) @ W      [M,256]x[256,128] -> [M,128]
#define BM 128
#define BK 16
#define TM 8
#define TN 8

__global__ __launch_bounds__(256) void k_gemm(const float* __restrict__ feat,
                                              const float* __restrict__ weight,
                                              int M) {
    __shared__ float As[BM][BK];
    __shared__ float Bs[BK][DOUT];

    const int block_row = blockIdx.x * BM;
    const int tid = threadIdx.x;
    const int tr = (tid / 16) * TM;
    const int tc = (tid % 16) * TN;

    float acc[TM][TN];
    #pragma unroll
    for (int i = 0; i < TM; i++)
        #pragma unroll
        for (int j = 0; j < TN; j++) acc[i][j] = 0.0f;

    for (int k0 = 0; k0 < DIN; k0 += BK) {
        #pragma unroll
        for (int i = 0; i < 2; i++) {
            int idx = tid + i * 256;
            int r   = idx >> 2;
            int c4  = (idx & 3) * 4;
            int grow = block_row + r;
            float4 v = make_float4(0.f, 0.f, 0.f, 0.f);
            float  s = 0.f;
            if (grow < M) {
                v = *(const float4*)&feat[(size_t)grow * DIN + k0 + c4];
                s = g_scout[grow];
            }
            *(float4*)&As[r][c4] = make_float4(v.x * s, v.y * s, v.z * s, v.w * s);
        }
        #pragma unroll
        for (int i = 0; i < 2; i++) {
            int idx = tid + i * 256;
            int r   = idx >> 5;
            int c4  = (idx & 31) * 4;
            *(float4*)&Bs[r][c4] = *(const float4*)&weight[(size_t)(k0 + r) * DOUT + c4];
        }
        __syncthreads();

        #pragma unroll
        for (int k = 0; k < BK; k++) {
            float a[TM], b[TN];
            #pragma unroll
            for (int i = 0; i < TM; i++) a[i] = As[tr + i][k];
            float4 b0 = *(float4*)&Bs[k][tc];
            float4 b1 = *(float4*)&Bs[k][tc + 4];
            b[0]=b0.x; b[1]=b0.y; b[2]=b0.z; b[3]=b0.w;
            b[4]=b1.x; b[5]=b1.y; b[6]=b1.z; b[7]=b1.w;
            #pragma unroll
            for (int i = 0; i < TM; i++)
                #pragma unroll
                for (int j = 0; j < TN; j++)
                    acc[i][j] = fmaf(a[i], b[j], acc[i][j]);
        }
        __syncthreads();
    }

    #pragma unroll
    for (int i = 0; i < TM; i++) {
        int grow = block_row + tr + i;
        if (grow < M) {
            #pragma unroll
            for (int j = 0; j < TN; j += 4)
                *(float4*)&g_h[(size_t)grow * DOUT + tc + j] =
                    make_float4(acc[i][j], acc[i][j+1], acc[i][j+2], acc[i][j+3]);
        }
    }
}

// ---------------------------------------------------------------- gather-agg
// One warp per dst node. Each lane owns 4 consecutive floats (float4) of the
// 128-wide row. Registers accumulate; single write to out. No atomics.
__global__ __launch_bounds__(256) void k_gather(float* __restrict__ out,
                                                const float* __restrict__ bias,
                                                int M) {
    long gid  = (long)blockIdx.x * blockDim.x + threadIdx.x;
    int  node = (int)(gid >> 5);
    int  lane = (int)(gid & 31);
    if (node >= M) return;

    int beg = g_off[node];
    int end = g_off[node + 1];

    const float4* hp = (const float4*)g_h;
    float4 acc = make_float4(0.f, 0.f, 0.f, 0.f);

    int e = beg;
    // 4-way unroll for MLP
    for (; e + 4 <= end; e += 4) {
        int s0 = g_csrc[e], s1 = g_csrc[e+1], s2 = g_csrc[e+2], s3 = g_csrc[e+3];
        float4 v0 = __ldg(hp + (size_t)s0 * 32 + lane);
        float4 v1 = __ldg(hp + (size_t)s1 * 32 + lane);
        float4 v2 = __ldg(hp + (size_t)s2 * 32 + lane);
        float4 v3 = __ldg(hp + (size_t)s3 * 32 + lane);
        acc.x += v0.x + v1.x + v2.x + v3.x;
        acc.y += v0.y + v1.y + v2.y + v3.y;
        acc.z += v0.z + v1.z + v2.z + v3.z;
        acc.w += v0.w + v1.w + v2.w + v3.w;
    }
    for (; e < end; e++) {
        int s = g_csrc[e];
        float4 v = __ldg(hp + (size_t)s * 32 + lane);
        acc.x += v.x; acc.y += v.y; acc.z += v.z; acc.w += v.w;
    }

    float sc = g_scin[node];
    float4 b = *(const float4*)&bias[lane * 4];
    float4 r = make_float4(fmaf(acc.x, sc, b.x), fmaf(acc.y, sc, b.y),
                           fmaf(acc.z, sc, b.z), fmaf(acc.w, sc, b.w));
    *((float4*)out + (size_t)node * 32 + lane) = r;
}

// ---------------------------------------------------------------- launch
extern "C" void kernel_launch(void* const* d_in, const int* in_sizes, int n_in,
                              void* d_out, int out_size) {
    const float* feat   = (const float*)d_in[0];
    const float* weight = (const float*)d_in[1];
    const float* bias   = (const float*)d_in[2];
    const int*   src    = (const int*)  d_in[3];
    const int*   dst    = (const int*)  d_in[4];

    int M  = in_sizes[0] / DIN;   // 100000
    int nE = in_sizes[3];         // 3200000
    int nb = (M + 255) / 256;     // scan blocks (391 <= 1024)

    k_zero_deg<<<(M + 255) / 256, 256>>>(M);
    k_count   <<<(nE + 255) / 256, 256>>>(src, dst, nE);
    k_scales  <<<(M + 255) / 256, 256>>>(M);

    k_scan1<<<nb, 256>>>(M);
    k_scan2<<<1, 1024>>>(nb);
    k_scan3<<<nb, 256>>>(M, nE);
    k_build<<<(nE + 255) / 256, 256>>>(src, dst, nE);

    k_gemm<<<(M + BM - 1) / BM, 256>>>(feat, weight, M);

    long gather_threads = (long)M * 32;
    k_gather<<<(unsigned)((gather_threads + 255) / 256), 256>>>((float*)d_out, bias, M);
}

// round 4
// speedup vs baseline: 2.3858x; 1.3807x over previous
#include <cuda_runtime.h>
#include <cuda_bf16.h>
#include <cstdint>

#define DIN   256
#define DOUT  128
#define NMAX  100000
#define EMAX  3200000

// ---------------- scratch (static device globals — allocation-free) ----------
__device__ float g_h   [(size_t)NMAX * DOUT];  // 51.2 MB: transformed features
__device__ int   g_outdeg[NMAX];
__device__ int   g_indeg [NMAX];
__device__ float g_scout [NMAX];               // out_deg^-1/2
__device__ float g_scin  [NMAX];               // in_deg^-1/2
__device__ int   g_off   [NMAX + 1];           // CSR offsets (by dst)
__device__ int   g_cursor[NMAX];               // placement cursors
__device__ int   g_bsum  [1024];               // block sums for scan
__device__ int   g_csrc  [EMAX];               // CSR payload: src node per slot
// Pre-split weight as B^T: [n][k] bf16 hi/lo (64 KB each)
__device__ __nv_bfloat16 g_bhi[DOUT * DIN];
__device__ __nv_bfloat16 g_blo[DOUT * DIN];

// ---------------------------------------------------------------- degree zero
__global__ void k_zero_deg(int n) {
    int i = blockIdx.x * blockDim.x + threadIdx.x;
    if (i < n) { g_outdeg[i] = 0; g_indeg[i] = 0; }
}

// ---------------------------------------------------------------- degree count
__global__ void k_count(const int* __restrict__ src, const int* __restrict__ dst, int nE) {
    int i = blockIdx.x * blockDim.x + threadIdx.x;
    if (i < nE) {
        atomicAdd(&g_outdeg[src[i]], 1);
        atomicAdd(&g_indeg [dst[i]], 1);
    }
}

// ---------------------------------------------------------------- scales
__global__ void k_scales(int n) {
    int i = blockIdx.x * blockDim.x + threadIdx.x;
    if (i < n) {
        g_scout[i] = rsqrtf(fmaxf((float)g_outdeg[i], 1.0f));
        g_scin [i] = rsqrtf(fmaxf((float)g_indeg [i], 1.0f));
    }
}

// ---------------------------------------------------------------- prep B split
// g_bhi[n][k] = bf16_hi(w[k][n]);  g_blo = bf16(w - hi). (B^T layout, k-major rows)
__global__ void k_prepB(const float* __restrict__ w) {
    int i = blockIdx.x * blockDim.x + threadIdx.x;
    if (i >= DIN * DOUT) return;
    int n = i / DIN, k = i % DIN;
    float v = w[(size_t)k * DOUT + n];
    __nv_bfloat16 hi = __float2bfloat16(v);
    __nv_bfloat16 lo = __float2bfloat16(v - __bfloat162float(hi));
    g_bhi[i] = hi;
    g_blo[i] = lo;
}

// ---------------------------------------------------------------- scan stage 1
__global__ __launch_bounds__(256) void k_scan1(int n) {
    __shared__ int sh[256];
    int i = blockIdx.x * 256 + threadIdx.x;
    int v = (i < n) ? g_indeg[i] : 0;
    sh[threadIdx.x] = v;
    __syncthreads();
    #pragma unroll
    for (int off = 1; off < 256; off <<= 1) {
        int t = (threadIdx.x >= off) ? sh[threadIdx.x - off] : 0;
        __syncthreads();
        sh[threadIdx.x] += t;
        __syncthreads();
    }
    if (i < n) g_off[i] = sh[threadIdx.x] - v;
    if (threadIdx.x == 255) g_bsum[blockIdx.x] = sh[255];
}

// ---------------------------------------------------------------- scan stage 2
__global__ __launch_bounds__(1024) void k_scan2(int nb) {
    __shared__ int sh[1024];
    int t = threadIdx.x;
    int v = (t < nb) ? g_bsum[t] : 0;
    sh[t] = v;
    __syncthreads();
    #pragma unroll
    for (int off = 1; off < 1024; off <<= 1) {
        int x = (t >= off) ? sh[t - off] : 0;
        __syncthreads();
        sh[t] += x;
        __syncthreads();
    }
    if (t < nb) g_bsum[t] = sh[t] - v;
}

// ---------------------------------------------------------------- scan stage 3
__global__ void k_scan3(int n, int nE) {
    int i = blockIdx.x * blockDim.x + threadIdx.x;
    if (i < n) {
        int o = g_off[i] + g_bsum[blockIdx.x];
        g_off[i] = o;
        g_cursor[i] = o;
    }
    if (i == 0) g_off[n] = nE;
}

// ---------------------------------------------------------------- CSR build
__global__ void k_build(const int* __restrict__ src, const int* __restrict__ dst, int nE) {
    int i = blockIdx.x * blockDim.x + threadIdx.x;
    if (i < nE) {
        int d = dst[i];
        int p = atomicAdd(&g_cursor[d], 1);
        g_csrc[p] = src[i];
    }
}

// ---------------------------------------------------------------- GEMM (HMMA bf16 3-split)
// h = (feat*scout) @ W via a_hi*b_hi + a_hi*b_lo + a_lo*b_hi (fp32 accum).
// CTA: 128 rows x N=128, K in 4 chunks of 64. 8 warps (4M x 2N), warp tile 32x64.
// mma.sync.aligned.m16n8k16.row.col.f32.bf16.bf16.f32
#define BK    64
#define PITCH 72   /* bf16 elems per smem row; bank = (4g+t)%32 -> conflict-free */

__device__ __forceinline__ void mma16816(float* d, const uint32_t* a, const uint32_t* b) {
    asm volatile(
        "mma.sync.aligned.m16n8k16.row.col.f32.bf16.bf16.f32 "
        "{%0,%1,%2,%3}, {%4,%5,%6,%7}, {%8,%9}, {%0,%1,%2,%3};"
        : "+f"(d[0]), "+f"(d[1]), "+f"(d[2]), "+f"(d[3])
        : "r"(a[0]), "r"(a[1]), "r"(a[2]), "r"(a[3]), "r"(b[0]), "r"(b[1]));
}

__global__ __launch_bounds__(256, 1) void k_gemm_mma(const float* __restrict__ feat, int M) {
    extern __shared__ __nv_bfloat16 sm[];
    __nv_bfloat16* Ah = sm;                    // [128][PITCH]
    __nv_bfloat16* Al = Ah + 128 * PITCH;
    __nv_bfloat16* Bh = Al + 128 * PITCH;      // [128 n][PITCH]
    __nv_bfloat16* Bl = Bh + 128 * PITCH;

    const int tid  = threadIdx.x;
    const int wid  = tid >> 5, lane = tid & 31;
    const int g    = lane >> 2, t = lane & 3;  // groupID, thread-in-group
    const int wm   = wid & 3, wn = wid >> 2;   // warp grid 4(M) x 2(N)
    const int brow = blockIdx.x * 128;

    float acc[2][8][4];
    #pragma unroll
    for (int m = 0; m < 2; m++)
        #pragma unroll
        for (int s = 0; s < 8; s++)
            #pragma unroll
            for (int q = 0; q < 4; q++) acc[m][s][q] = 0.f;

    for (int c = 0; c < 4; c++) {
        const int k0 = c * BK;
        // ---- load A chunk: 128 rows x 64 cols fp32, scale + split
        #pragma unroll
        for (int i = 0; i < 8; i++) {
            int idx = tid + i * 256;          // 0..2047
            int r   = idx >> 4;               // 0..127
            int c4  = (idx & 15) * 4;         // 0..60
            int gr  = brow + r;
            float4 v = make_float4(0.f, 0.f, 0.f, 0.f);
            float  s = 0.f;
            if (gr < M) {
                v = *(const float4*)&feat[(size_t)gr * DIN + k0 + c4];
                s = g_scout[gr];
            }
            v.x *= s; v.y *= s; v.z *= s; v.w *= s;
            __nv_bfloat162 h0 = __floats2bfloat162_rn(v.x, v.y);
            __nv_bfloat162 h1 = __floats2bfloat162_rn(v.z, v.w);
            __nv_bfloat162 l0 = __floats2bfloat162_rn(v.x - __bfloat162float(h0.x),
                                                      v.y - __bfloat162float(h0.y));
            __nv_bfloat162 l1 = __floats2bfloat162_rn(v.z - __bfloat162float(h1.x),
                                                      v.w - __bfloat162float(h1.y));
            *(uint2*)&Ah[r * PITCH + c4] = make_uint2(*(uint32_t*)&h0, *(uint32_t*)&h1);
            *(uint2*)&Al[r * PITCH + c4] = make_uint2(*(uint32_t*)&l0, *(uint32_t*)&l1);
        }
        // ---- copy B chunk from pre-split tables: 128 n-rows x 64 k (uint2 = 4 bf16)
        #pragma unroll
        for (int i = 0; i < 8; i++) {
            int idx = tid + i * 256;          // 0..2047
            int n   = idx >> 4;               // 0..127
            int j   = (idx & 15) * 4;         // 0..60
            *(uint2*)&Bh[n * PITCH + j] = *(const uint2*)&g_bhi[n * DIN + k0 + j];
            *(uint2*)&Bl[n * PITCH + j] = *(const uint2*)&g_blo[n * DIN + k0 + j];
        }
        __syncthreads();

        // ---- compute: 4 k-steps of 16
        #pragma unroll
        for (int ks = 0; ks < 4; ks++) {
            const int kk = ks * 16;
            uint32_t ah[2][4], al[2][4];
            #pragma unroll
            for (int m = 0; m < 2; m++) {
                int r0 = wm * 32 + m * 16 + g;
                ah[m][0] = *(uint32_t*)&Ah[ r0      * PITCH + kk + 2 * t];
                ah[m][1] = *(uint32_t*)&Ah[(r0 + 8) * PITCH + kk + 2 * t];
                ah[m][2] = *(uint32_t*)&Ah[ r0      * PITCH + kk + 8 + 2 * t];
                ah[m][3] = *(uint32_t*)&Ah[(r0 + 8) * PITCH + kk + 8 + 2 * t];
                al[m][0] = *(uint32_t*)&Al[ r0      * PITCH + kk + 2 * t];
                al[m][1] = *(uint32_t*)&Al[(r0 + 8) * PITCH + kk + 2 * t];
                al[m][2] = *(uint32_t*)&Al[ r0      * PITCH + kk + 8 + 2 * t];
                al[m][3] = *(uint32_t*)&Al[(r0 + 8) * PITCH + kk + 8 + 2 * t];
            }
            uint32_t bh[8][2], bl[8][2];
            #pragma unroll
            for (int s = 0; s < 8; s++) {
                int n0 = wn * 64 + s * 8 + g;
                bh[s][0] = *(uint32_t*)&Bh[n0 * PITCH + kk + 2 * t];
                bh[s][1] = *(uint32_t*)&Bh[n0 * PITCH + kk + 8 + 2 * t];
                bl[s][0] = *(uint32_t*)&Bl[n0 * PITCH + kk + 2 * t];
                bl[s][1] = *(uint32_t*)&Bl[n0 * PITCH + kk + 8 + 2 * t];
            }
            #pragma unroll
            for (int m = 0; m < 2; m++)
                #pragma unroll
                for (int s = 0; s < 8; s++) {
                    mma16816(acc[m][s], ah[m], bh[s]);
                    mma16816(acc[m][s], ah[m], bl[s]);
                    mma16816(acc[m][s], al[m], bh[s]);
                }
        }
        __syncthreads();
    }

    // ---- epilogue: write fp32 accumulators to g_h
    #pragma unroll
    for (int m = 0; m < 2; m++) {
        int r0 = brow + wm * 32 + m * 16 + g;
        int r1 = r0 + 8;
        #pragma unroll
        for (int s = 0; s < 8; s++) {
            int cb = wn * 64 + s * 8 + 2 * t;
            if (r0 < M) *(float2*)&g_h[(size_t)r0 * DOUT + cb] = make_float2(acc[m][s][0], acc[m][s][1]);
            if (r1 < M) *(float2*)&g_h[(size_t)r1 * DOUT + cb] = make_float2(acc[m][s][2], acc[m][s][3]);
        }
    }
}

#define GEMM_SMEM (4 * 128 * PITCH * 2)   /* 73728 B */

// ---------------------------------------------------------------- gather-agg
__global__ __launch_bounds__(256) void k_gather(float* __restrict__ out,
                                                const float* __restrict__ bias,
                                                int M) {
    long gid  = (long)blockIdx.x * blockDim.x + threadIdx.x;
    int  node = (int)(gid >> 5);
    int  lane = (int)(gid & 31);
    if (node >= M) return;

    int beg = g_off[node];
    int end = g_off[node + 1];

    const float4* hp = (const float4*)g_h;
    float4 acc = make_float4(0.f, 0.f, 0.f, 0.f);

    int e = beg;
    for (; e + 4 <= end; e += 4) {
        int s0 = g_csrc[e], s1 = g_csrc[e+1], s2 = g_csrc[e+2], s3 = g_csrc[e+3];
        float4 v0 = __ldg(hp + (size_t)s0 * 32 + lane);
        float4 v1 = __ldg(hp + (size_t)s1 * 32 + lane);
        float4 v2 = __ldg(hp + (size_t)s2 * 32 + lane);
        float4 v3 = __ldg(hp + (size_t)s3 * 32 + lane);
        acc.x += v0.x + v1.x + v2.x + v3.x;
        acc.y += v0.y + v1.y + v2.y + v3.y;
        acc.z += v0.z + v1.z + v2.z + v3.z;
        acc.w += v0.w + v1.w + v2.w + v3.w;
    }
    for (; e < end; e++) {
        int s = g_csrc[e];
        float4 v = __ldg(hp + (size_t)s * 32 + lane);
        acc.x += v.x; acc.y += v.y; acc.z += v.z; acc.w += v.w;
    }

    float sc = g_scin[node];
    float4 b = *(const float4*)&bias[lane * 4];
    float4 r = make_float4(fmaf(acc.x, sc, b.x), fmaf(acc.y, sc, b.y),
                           fmaf(acc.z, sc, b.z), fmaf(acc.w, sc, b.w));
    *((float4*)out + (size_t)node * 32 + lane) = r;
}

// ---------------------------------------------------------------- launch
extern "C" void kernel_launch(void* const* d_in, const int* in_sizes, int n_in,
                              void* d_out, int out_size) {
    const float* feat   = (const float*)d_in[0];
    const float* weight = (const float*)d_in[1];
    const float* bias   = (const float*)d_in[2];
    const int*   src    = (const int*)  d_in[3];
    const int*   dst    = (const int*)  d_in[4];

    int M  = in_sizes[0] / DIN;   // 100000
    int nE = in_sizes[3];         // 3200000
    int nb = (M + 255) / 256;     // scan blocks (<=1024)

    static int smem_set = 0;
    if (!smem_set) {
        cudaFuncSetAttribute(k_gemm_mma, cudaFuncAttributeMaxDynamicSharedMemorySize, GEMM_SMEM);
        smem_set = 1;
    }

    k_zero_deg<<<(M + 255) / 256, 256>>>(M);
    k_count   <<<(nE + 255) / 256, 256>>>(src, dst, nE);
    k_scales  <<<(M + 255) / 256, 256>>>(M);
    k_prepB   <<<(DIN * DOUT + 255) / 256, 256>>>(weight);

    k_scan1<<<nb, 256>>>(M);
    k_scan2<<<1, 1024>>>(nb);
    k_scan3<<<nb, 256>>>(M, nE);
    k_build<<<(nE + 255) / 256, 256>>>(src, dst, nE);

    k_gemm_mma<<<(M + 127) / 128, 256, GEMM_SMEM>>>(feat, M);

    long gather_threads = (long)M * 32;
    k_gather<<<(unsigned)((gather_threads + 255) / 256), 256>>>((float*)d_out, bias, M);
}

// round 5
// speedup vs baseline: 2.5352x; 1.0626x over previous
#include <cuda_runtime.h>
#include <cuda_bf16.h>
#include <cstdint>

#define DIN   256
#define DOUT  128
#define NMAX  100000
#define EMAX  3200000

// ---------------- scratch (static device globals — allocation-free) ----------
__device__ float g_h   [(size_t)NMAX * DOUT];  // 51.2 MB: transformed features (UNSCALED)
__device__ int   g_outdeg[NMAX];
__device__ int   g_indeg [NMAX];
__device__ float g_scout [NMAX];               // out_deg^-1/2
__device__ float g_scin  [NMAX];               // in_deg^-1/2
__device__ int   g_off   [NMAX + 1];           // CSR offsets (by dst)
__device__ int   g_cursor[NMAX];               // placement cursors
__device__ int   g_bsum  [1024];               // block sums for scan
__device__ int   g_csrc  [EMAX];               // CSR payload: src node per slot
// Pre-split weight as B^T: [n][k] bf16 hi/lo (64 KB each)
__device__ __nv_bfloat16 g_bhi[DOUT * DIN];
__device__ __nv_bfloat16 g_blo[DOUT * DIN];

// ---------------------------------------------------------------- degree zero
__global__ void k_zero_deg(int n) {
    int i = blockIdx.x * blockDim.x + threadIdx.x;
    if (i < n) { g_outdeg[i] = 0; g_indeg[i] = 0; }
}

// ---------------------------------------------------------------- degree count
__global__ void k_count(const int* __restrict__ src, const int* __restrict__ dst, int nE) {
    int i = blockIdx.x * blockDim.x + threadIdx.x;
    if (i < nE) {
        atomicAdd(&g_outdeg[src[i]], 1);
        atomicAdd(&g_indeg [dst[i]], 1);
    }
}

// ---------------------------------------------------------------- scales
__global__ void k_scales(int n) {
    int i = blockIdx.x * blockDim.x + threadIdx.x;
    if (i < n) {
        g_scout[i] = rsqrtf(fmaxf((float)g_outdeg[i], 1.0f));
        g_scin [i] = rsqrtf(fmaxf((float)g_indeg [i], 1.0f));
    }
}

// ---------------------------------------------------------------- prep B split
__global__ void k_prepB(const float* __restrict__ w) {
    int i = blockIdx.x * blockDim.x + threadIdx.x;
    if (i >= DIN * DOUT) return;
    int n = i / DIN, k = i % DIN;
    float v = w[(size_t)k * DOUT + n];
    __nv_bfloat16 hi = __float2bfloat16(v);
    __nv_bfloat16 lo = __float2bfloat16(v - __bfloat162float(hi));
    g_bhi[i] = hi;
    g_blo[i] = lo;
}

// ---------------------------------------------------------------- scan stage 1
__global__ __launch_bounds__(256) void k_scan1(int n) {
    __shared__ int sh[256];
    int i = blockIdx.x * 256 + threadIdx.x;
    int v = (i < n) ? g_indeg[i] : 0;
    sh[threadIdx.x] = v;
    __syncthreads();
    #pragma unroll
    for (int off = 1; off < 256; off <<= 1) {
        int t = (threadIdx.x >= off) ? sh[threadIdx.x - off] : 0;
        __syncthreads();
        sh[threadIdx.x] += t;
        __syncthreads();
    }
    if (i < n) g_off[i] = sh[threadIdx.x] - v;
    if (threadIdx.x == 255) g_bsum[blockIdx.x] = sh[255];
}

// ---------------------------------------------------------------- scan stage 2
__global__ __launch_bounds__(1024) void k_scan2(int nb) {
    __shared__ int sh[1024];
    int t = threadIdx.x;
    int v = (t < nb) ? g_bsum[t] : 0;
    sh[t] = v;
    __syncthreads();
    #pragma unroll
    for (int off = 1; off < 1024; off <<= 1) {
        int x = (t >= off) ? sh[t - off] : 0;
        __syncthreads();
        sh[t] += x;
        __syncthreads();
    }
    if (t < nb) g_bsum[t] = sh[t] - v;
}

// ---------------------------------------------------------------- scan stage 3
__global__ void k_scan3(int n, int nE) {
    int i = blockIdx.x * blockDim.x + threadIdx.x;
    if (i < n) {
        int o = g_off[i] + g_bsum[blockIdx.x];
        g_off[i] = o;
        g_cursor[i] = o;
    }
    if (i == 0) g_off[n] = nE;
}

// ---------------------------------------------------------------- CSR build
__global__ void k_build(const int* __restrict__ src, const int* __restrict__ dst, int nE) {
    int i = blockIdx.x * blockDim.x + threadIdx.x;
    if (i < nE) {
        int d = dst[i];
        int p = atomicAdd(&g_cursor[d], 1);
        g_csrc[p] = src[i];
    }
}

// ---------------------------------------------------------------- GEMM (HMMA bf16 3-split)
// h = feat @ W (no scale — scout folded into gather).
// CTA: 128 rows x N=128. B (full K=256, hi+lo) resident in smem; A in 4 chunks
// of 64 with register prefetch of the next chunk during MMA of the current.
#define BK      64
#define PITCH_A 72    /* bank = (4g+t)%32 -> conflict-free */
#define PITCH_B 264

__device__ __forceinline__ void mma16816(float* d, const uint32_t* a, const uint32_t* b) {
    asm volatile(
        "mma.sync.aligned.m16n8k16.row.col.f32.bf16.bf16.f32 "
        "{%0,%1,%2,%3}, {%4,%5,%6,%7}, {%8,%9}, {%0,%1,%2,%3};"
        : "+f"(d[0]), "+f"(d[1]), "+f"(d[2]), "+f"(d[3])
        : "r"(a[0]), "r"(a[1]), "r"(a[2]), "r"(a[3]), "r"(b[0]), "r"(b[1]));
}

#define GEMM_SMEM ((2 * 128 * PITCH_A + 2 * 128 * PITCH_B) * 2)  /* 171,776 B */

__global__ __launch_bounds__(256, 1) void k_gemm_mma(const float* __restrict__ feat, int M) {
    extern __shared__ __nv_bfloat16 sm[];
    __nv_bfloat16* Ah = sm;                         // [128][PITCH_A]
    __nv_bfloat16* Al = Ah + 128 * PITCH_A;
    __nv_bfloat16* Bh = Al + 128 * PITCH_A;         // [128 n][PITCH_B] full K
    __nv_bfloat16* Bl = Bh + 128 * PITCH_B;

    const int tid  = threadIdx.x;
    const int wid  = tid >> 5, lane = tid & 31;
    const int g    = lane >> 2, t = lane & 3;
    const int wm   = wid & 3, wn = wid >> 2;        // warp grid 4(M) x 2(N)
    const int brow = blockIdx.x * 128;

    // ---- B resident copy: 128 n-rows x 256 k, hi+lo (uint2 = 4 bf16)
    #pragma unroll
    for (int i = 0; i < 32; i++) {
        int idx = tid + i * 256;            // 0..8191
        int n   = idx >> 6;                 // 0..127
        int j   = (idx & 63) * 4;           // 0..252
        *(uint2*)&Bh[n * PITCH_B + j] = *(const uint2*)&g_bhi[n * DIN + j];
        *(uint2*)&Bl[n * PITCH_B + j] = *(const uint2*)&g_blo[n * DIN + j];
    }

    float acc[2][8][4];
    #pragma unroll
    for (int m = 0; m < 2; m++)
        #pragma unroll
        for (int s = 0; s < 8; s++)
            #pragma unroll
            for (int q = 0; q < 4; q++) acc[m][s][q] = 0.f;

    // Per-thread A-load geometry (fixed across chunks)
    const int lr  = (tid * 2) >> 5;        // not used; keep simple below
    float4 v[8];
    // prefetch chunk 0
    #pragma unroll
    for (int i = 0; i < 8; i++) {
        int idx = tid + i * 256;
        int r = idx >> 4, c4 = (idx & 15) * 4;
        int gr = brow + r;
        v[i] = (gr < M) ? *(const float4*)&feat[(size_t)gr * DIN + c4]
                        : make_float4(0.f, 0.f, 0.f, 0.f);
    }
    __syncthreads();   // B ready

    for (int c = 0; c < 4; c++) {
        // ---- split + store chunk c from regs
        #pragma unroll
        for (int i = 0; i < 8; i++) {
            int idx = tid + i * 256;
            int r = idx >> 4, c4 = (idx & 15) * 4;
            float4 x = v[i];
            __nv_bfloat162 h0 = __floats2bfloat162_rn(x.x, x.y);
            __nv_bfloat162 h1 = __floats2bfloat162_rn(x.z, x.w);
            __nv_bfloat162 l0 = __floats2bfloat162_rn(x.x - __bfloat162float(h0.x),
                                                      x.y - __bfloat162float(h0.y));
            __nv_bfloat162 l1 = __floats2bfloat162_rn(x.z - __bfloat162float(h1.x),
                                                      x.w - __bfloat162float(h1.y));
            *(uint2*)&Ah[r * PITCH_A + c4] = make_uint2(*(uint32_t*)&h0, *(uint32_t*)&h1);
            *(uint2*)&Al[r * PITCH_A + c4] = make_uint2(*(uint32_t*)&l0, *(uint32_t*)&l1);
        }
        __syncthreads();

        // ---- prefetch chunk c+1 (v regs dead now; LDGs overlap MMA below)
        if (c < 3) {
            #pragma unroll
            for (int i = 0; i < 8; i++) {
                int idx = tid + i * 256;
                int r = idx >> 4, c4 = (idx & 15) * 4;
                int gr = brow + r;
                v[i] = (gr < M) ? *(const float4*)&feat[(size_t)gr * DIN + (c + 1) * 64 + c4]
                                : make_float4(0.f, 0.f, 0.f, 0.f);
            }
        }

        // ---- compute chunk c: 4 k-steps of 16
        const int kb = c * BK;
        #pragma unroll
        for (int ks = 0; ks < 4; ks++) {
            const int kk = ks * 16;
            uint32_t ah[2][4], al[2][4];
            #pragma unroll
            for (int m = 0; m < 2; m++) {
                int r0 = wm * 32 + m * 16 + g;
                ah[m][0] = *(uint32_t*)&Ah[ r0      * PITCH_A + kk + 2 * t];
                ah[m][1] = *(uint32_t*)&Ah[(r0 + 8) * PITCH_A + kk + 2 * t];
                ah[m][2] = *(uint32_t*)&Ah[ r0      * PITCH_A + kk + 8 + 2 * t];
                ah[m][3] = *(uint32_t*)&Ah[(r0 + 8) * PITCH_A + kk + 8 + 2 * t];
                al[m][0] = *(uint32_t*)&Al[ r0      * PITCH_A + kk + 2 * t];
                al[m][1] = *(uint32_t*)&Al[(r0 + 8) * PITCH_A + kk + 2 * t];
                al[m][2] = *(uint32_t*)&Al[ r0      * PITCH_A + kk + 8 + 2 * t];
                al[m][3] = *(uint32_t*)&Al[(r0 + 8) * PITCH_A + kk + 8 + 2 * t];
            }
            #pragma unroll
            for (int s = 0; s < 8; s++) {
                int n0 = wn * 64 + s * 8 + g;
                uint32_t bh[2], bl[2];
                bh[0] = *(uint32_t*)&Bh[n0 * PITCH_B + kb + kk + 2 * t];
                bh[1] = *(uint32_t*)&Bh[n0 * PITCH_B + kb + kk + 8 + 2 * t];
                bl[0] = *(uint32_t*)&Bl[n0 * PITCH_B + kb + kk + 2 * t];
                bl[1] = *(uint32_t*)&Bl[n0 * PITCH_B + kb + kk + 8 + 2 * t];
                #pragma unroll
                for (int m = 0; m < 2; m++) {
                    mma16816(acc[m][s], ah[m], bh);
                    mma16816(acc[m][s], ah[m], bl);
                    mma16816(acc[m][s], al[m], bh);
                }
            }
        }
        __syncthreads();
    }

    // ---- epilogue
    #pragma unroll
    for (int m = 0; m < 2; m++) {
        int r0 = brow + wm * 32 + m * 16 + g;
        int r1 = r0 + 8;
        #pragma unroll
        for (int s = 0; s < 8; s++) {
            int cb = wn * 64 + s * 8 + 2 * t;
            if (r0 < M) *(float2*)&g_h[(size_t)r0 * DOUT + cb] = make_float2(acc[m][s][0], acc[m][s][1]);
            if (r1 < M) *(float2*)&g_h[(size_t)r1 * DOUT + cb] = make_float2(acc[m][s][2], acc[m][s][3]);
        }
    }
}

// ---------------------------------------------------------------- gather-agg
// acc += scout[src] * h[src]; final scale by scin[dst], add bias.
__global__ __launch_bounds__(256) void k_gather(float* __restrict__ out,
                                                const float* __restrict__ bias,
                                                int M) {
    long gid  = (long)blockIdx.x * blockDim.x + threadIdx.x;
    int  node = (int)(gid >> 5);
    int  lane = (int)(gid & 31);
    if (node >= M) return;

    int beg = g_off[node];
    int end = g_off[node + 1];

    const float4* hp = (const float4*)g_h;
    float4 acc = make_float4(0.f, 0.f, 0.f, 0.f);

    int e = beg;
    for (; e + 4 <= end; e += 4) {
        int s0 = g_csrc[e], s1 = g_csrc[e+1], s2 = g_csrc[e+2], s3 = g_csrc[e+3];
        float w0 = __ldg(&g_scout[s0]), w1 = __ldg(&g_scout[s1]);
        float w2 = __ldg(&g_scout[s2]), w3 = __ldg(&g_scout[s3]);
        float4 v0 = __ldg(hp + (size_t)s0 * 32 + lane);
        float4 v1 = __ldg(hp + (size_t)s1 * 32 + lane);
        float4 v2 = __ldg(hp + (size_t)s2 * 32 + lane);
        float4 v3 = __ldg(hp + (size_t)s3 * 32 + lane);
        acc.x = fmaf(v0.x, w0, fmaf(v1.x, w1, fmaf(v2.x, w2, fmaf(v3.x, w3, acc.x))));
        acc.y = fmaf(v0.y, w0, fmaf(v1.y, w1, fmaf(v2.y, w2, fmaf(v3.y, w3, acc.y))));
        acc.z = fmaf(v0.z, w0, fmaf(v1.z, w1, fmaf(v2.z, w2, fmaf(v3.z, w3, acc.z))));
        acc.w = fmaf(v0.w, w0, fmaf(v1.w, w1, fmaf(v2.w, w2, fmaf(v3.w, w3, acc.w))));
    }
    for (; e < end; e++) {
        int s = g_csrc[e];
        float w = __ldg(&g_scout[s]);
        float4 vv = __ldg(hp + (size_t)s * 32 + lane);
        acc.x = fmaf(vv.x, w, acc.x);
        acc.y = fmaf(vv.y, w, acc.y);
        acc.z = fmaf(vv.z, w, acc.z);
        acc.w = fmaf(vv.w, w, acc.w);
    }

    float sc = g_scin[node];
    float4 b = *(const float4*)&bias[lane * 4];
    float4 r = make_float4(fmaf(acc.x, sc, b.x), fmaf(acc.y, sc, b.y),
                           fmaf(acc.z, sc, b.z), fmaf(acc.w, sc, b.w));
    *((float4*)out + (size_t)node * 32 + lane) = r;
}

// ---------------------------------------------------------------- launch
extern "C" void kernel_launch(void* const* d_in, const int* in_sizes, int n_in,
                              void* d_out, int out_size) {
    const float* feat   = (const float*)d_in[0];
    const float* weight = (const float*)d_in[1];
    const float* bias   = (const float*)d_in[2];
    const int*   src    = (const int*)  d_in[3];
    const int*   dst    = (const int*)  d_in[4];

    int M  = in_sizes[0] / DIN;   // 100000
    int nE = in_sizes[3];         // 3200000
    int nb = (M + 255) / 256;     // scan blocks (<=1024)

    static cudaStream_t s2;
    static cudaEvent_t evFork, evJoin;
    static int inited = 0;
    if (!inited) {
        cudaFuncSetAttribute(k_gemm_mma, cudaFuncAttributeMaxDynamicSharedMemorySize, GEMM_SMEM);
        cudaStreamCreateWithFlags(&s2, cudaStreamNonBlocking);
        cudaEventCreateWithFlags(&evFork, cudaEventDisableTiming);
        cudaEventCreateWithFlags(&evJoin, cudaEventDisableTiming);
        inited = 1;
    }

    // ---- fork: GEMM branch on s2 (independent of graph prep)
    cudaEventRecord(evFork, 0);
    cudaStreamWaitEvent(s2, evFork, 0);
    k_prepB   <<<(DIN * DOUT + 255) / 256, 256, 0, s2>>>(weight);
    k_gemm_mma<<<(M + 127) / 128, 256, GEMM_SMEM, s2>>>(feat, M);
    cudaEventRecord(evJoin, s2);

    // ---- graph-prep branch on main stream
    k_zero_deg<<<(M + 255) / 256, 256>>>(M);
    k_count   <<<(nE + 255) / 256, 256>>>(src, dst, nE);
    k_scales  <<<(M + 255) / 256, 256>>>(M);
    k_scan1<<<nb, 256>>>(M);
    k_scan2<<<1, 1024>>>(nb);
    k_scan3<<<nb, 256>>>(M, nE);
    k_build<<<(nE + 255) / 256, 256>>>(src, dst, nE);

    // ---- join, then gather
    cudaStreamWaitEvent(0, evJoin, 0);
    long gather_threads = (long)M * 32;
    k_gather<<<(unsigned)((gather_threads + 255) / 256), 256>>>((float*)d_out, bias, M);
}

// round 6
// speedup vs baseline: 2.8058x; 1.1068x over previous
#include <cuda_runtime.h>
#include <cuda_bf16.h>
#include <cuda_fp16.h>
#include <cstdint>

#define DIN   256
#define DOUT  128
#define NMAX  100000
#define EMAX  3200000

// ---------------- scratch (static device globals — allocation-free) ----------
__device__ __align__(16) __half g_h16[(size_t)NMAX * DOUT];  // 25.6 MB, fp16 h (UNSCALED)
__device__ int   g_outdeg[NMAX];
__device__ int   g_indeg [NMAX];
__device__ float g_scout [NMAX];               // out_deg^-1/2
__device__ float g_scin  [NMAX];               // in_deg^-1/2
__device__ int   g_off   [NMAX + 1];           // CSR offsets (by dst)
__device__ int   g_cursor[NMAX];               // placement cursors
__device__ int   g_bsum  [1024];               // block sums for scan
__device__ int   g_csrc  [EMAX];               // CSR payload: src node per slot
// Pre-split weight as B^T: [n][k] bf16 hi/lo (64 KB each)
__device__ __nv_bfloat16 g_bhi[DOUT * DIN];
__device__ __nv_bfloat16 g_blo[DOUT * DIN];

// ---------------------------------------------------------------- degree zero
__global__ void k_zero_deg(int n) {
    int i = blockIdx.x * blockDim.x + threadIdx.x;
    if (i < n) { g_outdeg[i] = 0; g_indeg[i] = 0; }
}

// ---------------------------------------------------------------- degree count
__global__ void k_count(const int* __restrict__ src, const int* __restrict__ dst, int nE) {
    int i = blockIdx.x * blockDim.x + threadIdx.x;
    if (i < nE) {
        atomicAdd(&g_outdeg[src[i]], 1);
        atomicAdd(&g_indeg [dst[i]], 1);
    }
}

// ---------------------------------------------------------------- scales
__global__ void k_scales(int n) {
    int i = blockIdx.x * blockDim.x + threadIdx.x;
    if (i < n) {
        g_scout[i] = rsqrtf(fmaxf((float)g_outdeg[i], 1.0f));
        g_scin [i] = rsqrtf(fmaxf((float)g_indeg [i], 1.0f));
    }
}

// ---------------------------------------------------------------- prep B split
__global__ void k_prepB(const float* __restrict__ w) {
    int i = blockIdx.x * blockDim.x + threadIdx.x;
    if (i >= DIN * DOUT) return;
    int n = i / DIN, k = i % DIN;
    float v = w[(size_t)k * DOUT + n];
    __nv_bfloat16 hi = __float2bfloat16(v);
    __nv_bfloat16 lo = __float2bfloat16(v - __bfloat162float(hi));
    g_bhi[i] = hi;
    g_blo[i] = lo;
}

// ---------------------------------------------------------------- scan stage 1
__global__ __launch_bounds__(256) void k_scan1(int n) {
    __shared__ int sh[256];
    int i = blockIdx.x * 256 + threadIdx.x;
    int v = (i < n) ? g_indeg[i] : 0;
    sh[threadIdx.x] = v;
    __syncthreads();
    #pragma unroll
    for (int off = 1; off < 256; off <<= 1) {
        int t = (threadIdx.x >= off) ? sh[threadIdx.x - off] : 0;
        __syncthreads();
        sh[threadIdx.x] += t;
        __syncthreads();
    }
    if (i < n) g_off[i] = sh[threadIdx.x] - v;
    if (threadIdx.x == 255) g_bsum[blockIdx.x] = sh[255];
}

// ---------------------------------------------------------------- scan stage 2
__global__ __launch_bounds__(1024) void k_scan2(int nb) {
    __shared__ int sh[1024];
    int t = threadIdx.x;
    int v = (t < nb) ? g_bsum[t] : 0;
    sh[t] = v;
    __syncthreads();
    #pragma unroll
    for (int off = 1; off < 1024; off <<= 1) {
        int x = (t >= off) ? sh[t - off] : 0;
        __syncthreads();
        sh[t] += x;
        __syncthreads();
    }
    if (t < nb) g_bsum[t] = sh[t] - v;
}

// ---------------------------------------------------------------- scan stage 3
__global__ void k_scan3(int n, int nE) {
    int i = blockIdx.x * blockDim.x + threadIdx.x;
    if (i < n) {
        int o = g_off[i] + g_bsum[blockIdx.x];
        g_off[i] = o;
        g_cursor[i] = o;
    }
    if (i == 0) g_off[n] = nE;
}

// ---------------------------------------------------------------- CSR build
__global__ void k_build(const int* __restrict__ src, const int* __restrict__ dst, int nE) {
    int i = blockIdx.x * blockDim.x + threadIdx.x;
    if (i < nE) {
        int d = dst[i];
        int p = atomicAdd(&g_cursor[d], 1);
        g_csrc[p] = src[i];
    }
}

// ---------------------------------------------------------------- GEMM (HMMA bf16 3-split)
// h = feat @ W (no scale — scout folded into gather). Output fp16.
#define BK      64
#define PITCH_A 72
#define PITCH_B 264

__device__ __forceinline__ void mma16816(float* d, const uint32_t* a, const uint32_t* b) {
    asm volatile(
        "mma.sync.aligned.m16n8k16.row.col.f32.bf16.bf16.f32 "
        "{%0,%1,%2,%3}, {%4,%5,%6,%7}, {%8,%9}, {%0,%1,%2,%3};"
        : "+f"(d[0]), "+f"(d[1]), "+f"(d[2]), "+f"(d[3])
        : "r"(a[0]), "r"(a[1]), "r"(a[2]), "r"(a[3]), "r"(b[0]), "r"(b[1]));
}

#define GEMM_SMEM ((2 * 128 * PITCH_A + 2 * 128 * PITCH_B) * 2)  /* 171,776 B */

__global__ __launch_bounds__(256, 1) void k_gemm_mma(const float* __restrict__ feat, int M) {
    extern __shared__ __nv_bfloat16 sm[];
    __nv_bfloat16* Ah = sm;                         // [128][PITCH_A]
    __nv_bfloat16* Al = Ah + 128 * PITCH_A;
    __nv_bfloat16* Bh = Al + 128 * PITCH_A;         // [128 n][PITCH_B] full K
    __nv_bfloat16* Bl = Bh + 128 * PITCH_B;

    const int tid  = threadIdx.x;
    const int wid  = tid >> 5, lane = tid & 31;
    const int g    = lane >> 2, t = lane & 3;
    const int wm   = wid & 3, wn = wid >> 2;        // warp grid 4(M) x 2(N)
    const int brow = blockIdx.x * 128;

    // ---- B resident copy: 128 n-rows x 256 k, hi+lo
    #pragma unroll
    for (int i = 0; i < 32; i++) {
        int idx = tid + i * 256;
        int n   = idx >> 6;
        int j   = (idx & 63) * 4;
        *(uint2*)&Bh[n * PITCH_B + j] = *(const uint2*)&g_bhi[n * DIN + j];
        *(uint2*)&Bl[n * PITCH_B + j] = *(const uint2*)&g_blo[n * DIN + j];
    }

    float acc[2][8][4];
    #pragma unroll
    for (int m = 0; m < 2; m++)
        #pragma unroll
        for (int s = 0; s < 8; s++)
            #pragma unroll
            for (int q = 0; q < 4; q++) acc[m][s][q] = 0.f;

    float4 v[8];
    #pragma unroll
    for (int i = 0; i < 8; i++) {
        int idx = tid + i * 256;
        int r = idx >> 4, c4 = (idx & 15) * 4;
        int gr = brow + r;
        v[i] = (gr < M) ? *(const float4*)&feat[(size_t)gr * DIN + c4]
                        : make_float4(0.f, 0.f, 0.f, 0.f);
    }
    __syncthreads();   // B ready

    for (int c = 0; c < 4; c++) {
        #pragma unroll
        for (int i = 0; i < 8; i++) {
            int idx = tid + i * 256;
            int r = idx >> 4, c4 = (idx & 15) * 4;
            float4 x = v[i];
            __nv_bfloat162 h0 = __floats2bfloat162_rn(x.x, x.y);
            __nv_bfloat162 h1 = __floats2bfloat162_rn(x.z, x.w);
            __nv_bfloat162 l0 = __floats2bfloat162_rn(x.x - __bfloat162float(h0.x),
                                                      x.y - __bfloat162float(h0.y));
            __nv_bfloat162 l1 = __floats2bfloat162_rn(x.z - __bfloat162float(h1.x),
                                                      x.w - __bfloat162float(h1.y));
            *(uint2*)&Ah[r * PITCH_A + c4] = make_uint2(*(uint32_t*)&h0, *(uint32_t*)&h1);
            *(uint2*)&Al[r * PITCH_A + c4] = make_uint2(*(uint32_t*)&l0, *(uint32_t*)&l1);
        }
        __syncthreads();

        if (c < 3) {
            #pragma unroll
            for (int i = 0; i < 8; i++) {
                int idx = tid + i * 256;
                int r = idx >> 4, c4 = (idx & 15) * 4;
                int gr = brow + r;
                v[i] = (gr < M) ? *(const float4*)&feat[(size_t)gr * DIN + (c + 1) * 64 + c4]
                                : make_float4(0.f, 0.f, 0.f, 0.f);
            }
        }

        const int kb = c * BK;
        #pragma unroll
        for (int ks = 0; ks < 4; ks++) {
            const int kk = ks * 16;
            uint32_t ah[2][4], al[2][4];
            #pragma unroll
            for (int m = 0; m < 2; m++) {
                int r0 = wm * 32 + m * 16 + g;
                ah[m][0] = *(uint32_t*)&Ah[ r0      * PITCH_A + kk + 2 * t];
                ah[m][1] = *(uint32_t*)&Ah[(r0 + 8) * PITCH_A + kk + 2 * t];
                ah[m][2] = *(uint32_t*)&Ah[ r0      * PITCH_A + kk + 8 + 2 * t];
                ah[m][3] = *(uint32_t*)&Ah[(r0 + 8) * PITCH_A + kk + 8 + 2 * t];
                al[m][0] = *(uint32_t*)&Al[ r0      * PITCH_A + kk + 2 * t];
                al[m][1] = *(uint32_t*)&Al[(r0 + 8) * PITCH_A + kk + 2 * t];
                al[m][2] = *(uint32_t*)&Al[ r0      * PITCH_A + kk + 8 + 2 * t];
                al[m][3] = *(uint32_t*)&Al[(r0 + 8) * PITCH_A + kk + 8 + 2 * t];
            }
            #pragma unroll
            for (int s = 0; s < 8; s++) {
                int n0 = wn * 64 + s * 8 + g;
                uint32_t bh[2], bl[2];
                bh[0] = *(uint32_t*)&Bh[n0 * PITCH_B + kb + kk + 2 * t];
                bh[1] = *(uint32_t*)&Bh[n0 * PITCH_B + kb + kk + 8 + 2 * t];
                bl[0] = *(uint32_t*)&Bl[n0 * PITCH_B + kb + kk + 2 * t];
                bl[1] = *(uint32_t*)&Bl[n0 * PITCH_B + kb + kk + 8 + 2 * t];
                #pragma unroll
                for (int m = 0; m < 2; m++) {
                    mma16816(acc[m][s], ah[m], bh);
                    mma16816(acc[m][s], ah[m], bl);
                    mma16816(acc[m][s], al[m], bh);
                }
            }
        }
        __syncthreads();
    }

    // ---- epilogue: fp16 output
    #pragma unroll
    for (int m = 0; m < 2; m++) {
        int r0 = brow + wm * 32 + m * 16 + g;
        int r1 = r0 + 8;
        #pragma unroll
        for (int s = 0; s < 8; s++) {
            int cb = wn * 64 + s * 8 + 2 * t;
            if (r0 < M) *(__half2*)&g_h16[(size_t)r0 * DOUT + cb] =
                __floats2half2_rn(acc[m][s][0], acc[m][s][1]);
            if (r1 < M) *(__half2*)&g_h16[(size_t)r1 * DOUT + cb] =
                __floats2half2_rn(acc[m][s][2], acc[m][s][3]);
        }
    }
}

// ---------------------------------------------------------------- gather-agg
// Half-warp (16 lanes) per dst node; lane owns 8 consecutive cols (uint4 of fp16).
// acc += scout[src] * h16[src]; out = acc*scin + bias.
__global__ __launch_bounds__(256) void k_gather(float* __restrict__ out,
                                                const float* __restrict__ bias,
                                                int M) {
    long gid  = (long)blockIdx.x * blockDim.x + threadIdx.x;
    int  node = (int)(gid >> 4);
    int  lig  = (int)(gid & 15);          // lane in 16-lane group
    if (node >= M) return;

    int beg = g_off[node];
    int end = g_off[node + 1];

    const uint4* hp = (const uint4*)g_h16;   // row = 16 uint4 (128 halves)
    float acc[8];
    #pragma unroll
    for (int j = 0; j < 8; j++) acc[j] = 0.f;

    int e = beg;
    for (; e + 4 <= end; e += 4) {
        int s0 = __ldg(&g_csrc[e]),   s1 = __ldg(&g_csrc[e+1]);
        int s2 = __ldg(&g_csrc[e+2]), s3 = __ldg(&g_csrc[e+3]);
        float w0 = __ldg(&g_scout[s0]), w1 = __ldg(&g_scout[s1]);
        float w2 = __ldg(&g_scout[s2]), w3 = __ldg(&g_scout[s3]);
        uint4 q0 = __ldg(hp + (size_t)s0 * 16 + lig);
        uint4 q1 = __ldg(hp + (size_t)s1 * 16 + lig);
        uint4 q2 = __ldg(hp + (size_t)s2 * 16 + lig);
        uint4 q3 = __ldg(hp + (size_t)s3 * 16 + lig);
        #pragma unroll
        for (int p = 0; p < 4; p++) {
            uint32_t u0 = (&q0.x)[p], u1 = (&q1.x)[p], u2 = (&q2.x)[p], u3 = (&q3.x)[p];
            float2 f0 = __half22float2(*(__half2*)&u0);
            float2 f1 = __half22float2(*(__half2*)&u1);
            float2 f2 = __half22float2(*(__half2*)&u2);
            float2 f3 = __half22float2(*(__half2*)&u3);
            acc[2*p]   = fmaf(f0.x, w0, fmaf(f1.x, w1, fmaf(f2.x, w2, fmaf(f3.x, w3, acc[2*p]))));
            acc[2*p+1] = fmaf(f0.y, w0, fmaf(f1.y, w1, fmaf(f2.y, w2, fmaf(f3.y, w3, acc[2*p+1]))));
        }
    }
    for (; e < end; e++) {
        int s = __ldg(&g_csrc[e]);
        float w = __ldg(&g_scout[s]);
        uint4 q = __ldg(hp + (size_t)s * 16 + lig);
        #pragma unroll
        for (int p = 0; p < 4; p++) {
            uint32_t u = (&q.x)[p];
            float2 f = __half22float2(*(__half2*)&u);
            acc[2*p]   = fmaf(f.x, w, acc[2*p]);
            acc[2*p+1] = fmaf(f.y, w, acc[2*p+1]);
        }
    }

    float sc = g_scin[node];
    const float4* bp = (const float4*)&bias[lig * 8];
    float4 b0 = bp[0], b1 = bp[1];
    float4 r0 = make_float4(fmaf(acc[0], sc, b0.x), fmaf(acc[1], sc, b0.y),
                            fmaf(acc[2], sc, b0.z), fmaf(acc[3], sc, b0.w));
    float4 r1 = make_float4(fmaf(acc[4], sc, b1.x), fmaf(acc[5], sc, b1.y),
                            fmaf(acc[6], sc, b1.z), fmaf(acc[7], sc, b1.w));
    float4* op = (float4*)&out[(size_t)node * DOUT + lig * 8];
    op[0] = r0;
    op[1] = r1;
}

// ---------------------------------------------------------------- launch
extern "C" void kernel_launch(void* const* d_in, const int* in_sizes, int n_in,
                              void* d_out, int out_size) {
    const float* feat   = (const float*)d_in[0];
    const float* weight = (const float*)d_in[1];
    const float* bias   = (const float*)d_in[2];
    const int*   src    = (const int*)  d_in[3];
    const int*   dst    = (const int*)  d_in[4];

    int M  = in_sizes[0] / DIN;   // 100000
    int nE = in_sizes[3];         // 3200000
    int nb = (M + 255) / 256;

    static cudaStream_t s2;
    static cudaEvent_t evFork, evJoin;
    static int inited = 0;
    if (!inited) {
        cudaFuncSetAttribute(k_gemm_mma, cudaFuncAttributeMaxDynamicSharedMemorySize, GEMM_SMEM);
        cudaStreamCreateWithFlags(&s2, cudaStreamNonBlocking);
        cudaEventCreateWithFlags(&evFork, cudaEventDisableTiming);
        cudaEventCreateWithFlags(&evJoin, cudaEventDisableTiming);
        inited = 1;
    }

    // ---- fork: GEMM branch on s2
    cudaEventRecord(evFork, 0);
    cudaStreamWaitEvent(s2, evFork, 0);
    k_prepB   <<<(DIN * DOUT + 255) / 256, 256, 0, s2>>>(weight);
    k_gemm_mma<<<(M + 127) / 128, 256, GEMM_SMEM, s2>>>(feat, M);
    cudaEventRecord(evJoin, s2);

    // ---- graph-prep branch on main stream
    k_zero_deg<<<(M + 255) / 256, 256>>>(M);
    k_count   <<<(nE + 255) / 256, 256>>>(src, dst, nE);
    k_scales  <<<(M + 255) / 256, 256>>>(M);
    k_scan1<<<nb, 256>>>(M);
    k_scan2<<<1, 1024>>>(nb);
    k_scan3<<<nb, 256>>>(M, nE);
    k_build<<<(nE + 255) / 256, 256>>>(src, dst, nE);

    // ---- join, then gather
    cudaStreamWaitEvent(0, evJoin, 0);
    long gather_threads = (long)M * 16;
    k_gather<<<(unsigned)((gather_threads + 255) / 256), 256>>>((float*)d_out, bias, M);
}